// round 14
// baseline (speedup 1.0000x reference)
#include <cuda_runtime.h>
#include <math.h>
#include <stdint.h>

#define DIMC 384
#define B_   8
#define HH   56
#define WW   56
#define T1   3136
#define H2   28
#define W2   28
#define T2   784
#define NHEADS 6
#define HD   64
#define EPSBN 1e-5f
#define ATT_SCALE 0.05103103630798288f   /* 384^-0.5 (full dim, per reference) */
#define LOG2E 1.4426950408889634f
#define WN (DIMC * DIMC)

// ---------------- scratch ---------------------------------------------------
__device__ float g_qf[B_ * T1 * DIMC];
__device__ float g_kf[B_ * T2 * DIMC];
__device__ float g_vf[B_ * T2 * DIMC];
__device__ float g_qp[B_ * T1 * DIMC];
__device__ float g_kp[B_ * T2 * DIMC];
__device__ float g_vp[B_ * T2 * DIMC];
__device__ float g_ob[B_ * T1 * DIMC];
__device__ float g_wr[4 * WN];          // tf32-rounded wq, wk, wv, w_last

// ---------------- helpers ---------------------------------------------------
__device__ __forceinline__ float tf32r(float x) {
    uint32_t u;
    asm("cvt.rna.tf32.f32 %0, %1;" : "=r"(u) : "f"(x));
    return __uint_as_float(u);
}

__device__ __forceinline__ void mma8(float* d, const uint32_t* a, uint32_t b0, uint32_t b1) {
    asm volatile(
        "mma.sync.aligned.m16n8k8.row.col.f32.tf32.tf32.f32 "
        "{%0,%1,%2,%3}, {%4,%5,%6,%7}, {%8,%9}, {%0,%1,%2,%3};\n"
        : "+f"(d[0]), "+f"(d[1]), "+f"(d[2]), "+f"(d[3])
        : "r"(a[0]), "r"(a[1]), "r"(a[2]), "r"(a[3]), "r"(b0), "r"(b1));
}

__device__ __forceinline__ void cpa16(uint32_t dst, const void* src) {
    asm volatile("cp.async.cg.shared.global [%0], [%1], 16;" :: "r"(dst), "l"(src));
}
__device__ __forceinline__ void cpa16z(uint32_t dst, const void* src, int sz) {
    asm volatile("cp.async.cg.shared.global [%0], [%1], 16, %2;" :: "r"(dst), "l"(src), "r"(sz));
}
__device__ __forceinline__ void cpa_commit() {
    asm volatile("cp.async.commit_group;");
}
__device__ __forceinline__ uint32_t smem_u32(const void* p) {
    return (uint32_t)__cvta_generic_to_shared(p);
}

// ---------------- prep: round weight matrices to tf32 ------------------------
__global__ __launch_bounds__(256) void round_w_k(
    const float* __restrict__ wq, const float* __restrict__ wk,
    const float* __restrict__ wv, const float* __restrict__ wl)
{
    int i = blockIdx.x * 256 + threadIdx.x;
    if (i < 4 * WN) {
        int m = i / WN, j = i - m * WN;
        const float* s = (m == 0) ? wq : (m == 1) ? wk : (m == 2) ? wv : wl;
        g_wr[i] = tf32r(s[j]);
    }
}

// ---------------- conv bodies (as device functions) --------------------------
__device__ __forceinline__ void dwconv_s1_body(
    int by,
    const float* __restrict__ x, const float* __restrict__ cw,
    const float* __restrict__ gs, const float* __restrict__ gb,
    const float* __restrict__ gm, const float* __restrict__ gv,
    float* __restrict__ out)
{
    const int b  = by / HH, y = by % HH;
    const int c  = threadIdx.x;

    const float w0 = cw[c*9+0], w1 = cw[c*9+1], w2 = cw[c*9+2];
    const float w3 = cw[c*9+3], w4 = cw[c*9+4], w5 = cw[c*9+5];
    const float w6 = cw[c*9+6], w7 = cw[c*9+7], w8 = cw[c*9+8];
    const float inv = rsqrtf(gv[c] + EPSBN);
    const float sc  = gs[c] * inv;
    const float bb  = gb[c] - gm[c] * sc;

    const float* base = x + (size_t)b * T1 * DIMC + c;
    const bool v0 = (y > 0), v2 = (y < HH - 1);
    const float* r0 = base + (size_t)(y - 1) * WW * DIMC;
    const float* r1 = base + (size_t)y * WW * DIMC;
    const float* r2 = base + (size_t)(y + 1) * WW * DIMC;
    float* op = out + ((size_t)b * T1 + (size_t)y * WW) * DIMC + c;

    float a0 = 0.f, a1 = 0.f, a2 = 0.f;
    float b0 = v0 ? r0[0] : 0.f;
    float b1 = r1[0];
    float b2 = v2 ? r2[0] : 0.f;
    float c0 = v0 ? r0[DIMC] : 0.f;
    float c1 = r1[DIMC];
    float c2 = v2 ? r2[DIMC] : 0.f;

    #pragma unroll 4
    for (int xw = 0; xw < WW; xw++) {
        float acc = a0*w0 + b0*w1 + c0*w2
                  + a1*w3 + b1*w4 + c1*w5
                  + a2*w6 + b2*w7 + c2*w8;
        op[(size_t)xw * DIMC] = tf32r(acc * sc + bb);
        a0 = b0; a1 = b1; a2 = b2;
        b0 = c0; b1 = c1; b2 = c2;
        if (xw + 2 < WW) {
            size_t off = (size_t)(xw + 2) * DIMC;
            c0 = v0 ? r0[off] : 0.f;
            c1 = r1[off];
            c2 = v2 ? r2[off] : 0.f;
        } else { c0 = c1 = c2 = 0.f; }
    }
}

__device__ __forceinline__ void dwconv_s2_body(
    int by,
    const float* __restrict__ x,
    const float* __restrict__ cwk, const float* __restrict__ ksc, const float* __restrict__ kbi,
    const float* __restrict__ kmu, const float* __restrict__ kva,
    const float* __restrict__ cwv, const float* __restrict__ vsc, const float* __restrict__ vbi,
    const float* __restrict__ vmu, const float* __restrict__ vva,
    float* __restrict__ outk, float* __restrict__ outv)
{
    const int b  = by / H2, oy = by % H2;
    const int c  = threadIdx.x;
    const int y  = 2 * oy;

    float wk[9], wv[9];
    #pragma unroll
    for (int i = 0; i < 9; i++) { wk[i] = cwk[c*9+i]; wv[i] = cwv[c*9+i]; }
    const float invk = rsqrtf(kva[c] + EPSBN);
    const float sck  = ksc[c] * invk;
    const float bbk  = kbi[c] - kmu[c] * sck;
    const float invv = rsqrtf(vva[c] + EPSBN);
    const float scv  = vsc[c] * invv;
    const float bbv  = vbi[c] - vmu[c] * scv;

    const float* base = x + (size_t)b * T1 * DIMC + c;
    const bool v0 = (y > 0), v2 = (y < HH - 1);
    const float* r0 = base + (size_t)(y - 1) * WW * DIMC;
    const float* r1 = base + (size_t)y * WW * DIMC;
    const float* r2 = base + (size_t)(y + 1) * WW * DIMC;
    float* opk = outk + ((size_t)b * T2 + (size_t)oy * W2) * DIMC + c;
    float* opv = outv + ((size_t)b * T2 + (size_t)oy * W2) * DIMC + c;

    float a0 = 0.f, a1 = 0.f, a2 = 0.f;
    float b0 = v0 ? r0[0] : 0.f, b1 = r1[0], b2 = v2 ? r2[0] : 0.f;
    float c0 = v0 ? r0[DIMC] : 0.f, c1 = r1[DIMC], c2 = v2 ? r2[DIMC] : 0.f;

    #pragma unroll 2
    for (int ox = 0; ox < W2; ox++) {
        float ak = a0*wk[0] + b0*wk[1] + c0*wk[2]
                 + a1*wk[3] + b1*wk[4] + c1*wk[5]
                 + a2*wk[6] + b2*wk[7] + c2*wk[8];
        float av = a0*wv[0] + b0*wv[1] + c0*wv[2]
                 + a1*wv[3] + b1*wv[4] + c1*wv[5]
                 + a2*wv[6] + b2*wv[7] + c2*wv[8];
        opk[(size_t)ox * DIMC] = tf32r(ak * sck + bbk);
        opv[(size_t)ox * DIMC] = tf32r(av * scv + bbv);
        if (ox + 1 < W2) {
            size_t o1 = (size_t)(2*ox + 2) * DIMC;
            size_t o2 = (size_t)(2*ox + 3) * DIMC;
            a0 = c0; a1 = c1; a2 = c2;
            b0 = v0 ? r0[o1] : 0.f; b1 = r1[o1]; b2 = v2 ? r2[o1] : 0.f;
            c0 = v0 ? r0[o2] : 0.f; c1 = r1[o2]; c2 = v2 ? r2[o2] : 0.f;
        }
    }
}

__global__ __launch_bounds__(DIMC) void conv_fused(
    const float* __restrict__ x,
    const float* __restrict__ cq,  const float* __restrict__ qsc, const float* __restrict__ qbi,
    const float* __restrict__ qmu, const float* __restrict__ qva,
    const float* __restrict__ cwk, const float* __restrict__ ksc, const float* __restrict__ kbi,
    const float* __restrict__ kmu, const float* __restrict__ kva,
    const float* __restrict__ cwv, const float* __restrict__ vsc, const float* __restrict__ vbi,
    const float* __restrict__ vmu, const float* __restrict__ vva,
    float* __restrict__ outq, float* __restrict__ outk, float* __restrict__ outv)
{
    const int bx = blockIdx.x;
    if (bx < B_ * HH) {
        dwconv_s1_body(bx, x, cq, qsc, qbi, qmu, qva, outq);
    } else {
        dwconv_s2_body(bx - B_ * HH, x, cwk, ksc, kbi, kmu, kva,
                       cwv, vsc, vbi, vmu, vva, outk, outv);
    }
}

// ---------------- tf32 GEMM body (round-9 verified) --------------------------
__device__ __forceinline__ void gemm_body(
    const float* __restrict__ A, const float* __restrict__ W,
    const float* __restrict__ bias, float* __restrict__ C,
    float oscale, int rnd, int row0, int col0)
{
    __shared__ float As[2][128 * 32];
    __shared__ float Ws[2][64 * 32];

    const int tid = threadIdx.x;
    const int w = tid >> 5, lane = tid & 31;
    const int g = lane >> 2, t = lane & 3;
    const int wm = (w & 1) * 64, wn = (w >> 1) * 32;

    float acc[4][4][4] = {};

    auto load_stage = [&](int s, int k0) {
        uint32_t abase = smem_u32(As[s]);
        uint32_t wbase = smem_u32(Ws[s]);
        #pragma unroll
        for (int p = 0; p < 8; p++) {
            int idx = tid + p * 128;
            int r = idx >> 3, j = idx & 7;
            cpa16(abase + r * 128 + ((j ^ (r & 7)) << 4),
                  A + (size_t)(row0 + r) * DIMC + k0 + j * 4);
        }
        #pragma unroll
        for (int p = 0; p < 4; p++) {
            int idx = tid + p * 128;
            int r = idx >> 3, j = idx & 7;
            cpa16(wbase + r * 128 + ((j ^ (r & 7)) << 4),
                  W + (size_t)(col0 + r) * DIMC + k0 + j * 4);
        }
        cpa_commit();
    };

    load_stage(0, 0);
    load_stage(1, 32);

    for (int ks = 0; ks < 12; ks++) {
        const int s = ks & 1;
        asm volatile("cp.async.wait_group 1;");
        __syncthreads();
        const float* Ac = As[s];
        const float* Wc = Ws[s];
        #pragma unroll
        for (int kb = 0; kb < 4; kb++) {
            uint32_t af[4][4];
            #pragma unroll
            for (int mi = 0; mi < 4; mi++) {
                int r0i = wm + mi*16 + g;
                int c0i = (((kb*2    ) ^ g) << 2) + t;
                int c1i = (((kb*2 + 1) ^ g) << 2) + t;
                af[mi][0] = __float_as_uint(Ac[ r0i      * 32 + c0i]);
                af[mi][1] = __float_as_uint(Ac[(r0i + 8) * 32 + c0i]);
                af[mi][2] = __float_as_uint(Ac[ r0i      * 32 + c1i]);
                af[mi][3] = __float_as_uint(Ac[(r0i + 8) * 32 + c1i]);
            }
            #pragma unroll
            for (int ni = 0; ni < 4; ni++) {
                int nr = wn + ni*8 + g;
                uint32_t b0 = __float_as_uint(Wc[nr * 32 + (((kb*2    ) ^ g) << 2) + t]);
                uint32_t b1 = __float_as_uint(Wc[nr * 32 + (((kb*2 + 1) ^ g) << 2) + t]);
                #pragma unroll
                for (int mi = 0; mi < 4; mi++) mma8(acc[mi][ni], af[mi], b0, b1);
            }
        }
        __syncthreads();
        if (ks + 2 < 12) load_stage(s, (ks + 2) * 32);
        else cpa_commit();
    }

    #pragma unroll
    for (int mi = 0; mi < 4; mi++) {
        int r0 = row0 + wm + mi*16 + g;
        #pragma unroll
        for (int ni = 0; ni < 4; ni++) {
            int cc = col0 + wn + ni*8 + 2*t;
            float b0f = 0.f, b1f = 0.f;
            if (bias) { b0f = bias[cc]; b1f = bias[cc+1]; }
            float v0 = acc[mi][ni][0] * oscale + b0f;
            float v1 = acc[mi][ni][1] * oscale + b1f;
            float v2 = acc[mi][ni][2] * oscale + b0f;
            float v3 = acc[mi][ni][3] * oscale + b1f;
            if (rnd) { v0 = tf32r(v0); v1 = tf32r(v1); v2 = tf32r(v2); v3 = tf32r(v3); }
            *(float2*)&C[(size_t)r0 * DIMC + cc]       = make_float2(v0, v1);
            *(float2*)&C[(size_t)(r0 + 8) * DIMC + cc] = make_float2(v2, v3);
        }
    }
}

__global__ __launch_bounds__(128) void proj_fused(
    const float* __restrict__ qf, const float* __restrict__ kf,
    const float* __restrict__ vf,
    float* __restrict__ qp, float* __restrict__ kp, float* __restrict__ vp)
{
    const int z  = blockIdx.z;
    const int by = blockIdx.y;
    if (z > 0 && by >= (B_ * T2) / 128) return;

    const float* A = (z == 0) ? qf : (z == 1) ? kf : vf;
    const float* W = g_wr + z * WN;
    float*       C = (z == 0) ? qp : (z == 1) ? kp : vp;
    const float oscale = (z == 1) ? (ATT_SCALE * LOG2E) : 1.0f;

    gemm_body(A, W, nullptr, C, oscale, 1, by * 128, blockIdx.x * 64);
}

__global__ __launch_bounds__(128) void proj_last(
    const float* __restrict__ ob, const float* __restrict__ bias,
    float* __restrict__ out)
{
    gemm_body(ob, g_wr + 3 * WN, bias, out, 1.0f, 0,
              blockIdx.y * 128, blockIdx.x * 64);
}

// ---------------- tf32 flash attention: m=16/warp, 4 blocks/SM ---------------
// 64-query tile per block, 128 threads / 4 warps; warp w owns rows 16w..16w+15.
// Half the per-thread state of the m=32 version -> 4 blocks/SM (16 warps),
// doubling latency hiding for the softmax/shuffle interludes.
// No-max streaming softmax (round-12 verified); 3 KV buffers, 1 barrier/tile.
__global__ __launch_bounds__(128, 4) void attn_cp(
    const float* __restrict__ qp_, const float* __restrict__ kp_,
    const float* __restrict__ vp_, float* __restrict__ ob_)
{
    __shared__ float Ks[3][32 * 64];
    __shared__ float Vs[3][32 * 64];

    const int tid = threadIdx.x;
    const int w = tid >> 5, lane = tid & 31;
    const int g = lane >> 2, t = lane & 3;
    const int q0 = blockIdx.x * 64;
    const int h  = blockIdx.y;
    const int b  = blockIdx.z;

    const float* qp = qp_ + (size_t)b * T1 * DIMC + h * HD;
    const float* kp = kp_ + (size_t)b * T2 * DIMC + h * HD;
    const float* vp = vp_ + (size_t)b * T2 * DIMC + h * HD;

    const int kr = tid >> 4;
    const int kj = tid & 15;

    auto load_kv = [&](int buf, int kk0) {
        uint32_t kbase = smem_u32(Ks[buf]);
        uint32_t vbase = smem_u32(Vs[buf]);
        #pragma unroll
        for (int p = 0; p < 4; p++) {
            int r = kr + 8 * p;
            int key = kk0 + r;
            int ok  = (key < T2) ? 16 : 0;
            int kcl = (key < T2) ? key : (T2 - 1);
            cpa16z(kbase + r * 256 + ((kj ^ (r & 7)) << 4),
                   kp + (size_t)kcl * DIMC + kj * 4, ok);
            cpa16z(vbase + r * 256 + ((kj ^ (2 * (r & 3))) << 4),
                   vp + (size_t)kcl * DIMC + kj * 4, ok);
        }
        cpa_commit();
    };

    load_kv(0, 0);
    load_kv(1, 32);

    // Persistent Q fragments: ONE 16-row set per warp (rows always valid:
    // T1 = 3136 = 49*64, so q0+63 < T1).
    const int ra = q0 + w * 16 + g;
    const int rb = ra + 8;
    uint32_t qa[8][4];
    {
        const float* pa = qp + (size_t)ra * DIMC;
        const float* pb = qp + (size_t)rb * DIMC;
        #pragma unroll
        for (int kb = 0; kb < 8; kb++) {
            qa[kb][0] = __float_as_uint(pa[kb*8 + t]);
            qa[kb][1] = __float_as_uint(pb[kb*8 + t]);
            qa[kb][2] = __float_as_uint(pa[kb*8 + t + 4]);
            qa[kb][3] = __float_as_uint(pb[kb*8 + t + 4]);
        }
    }

    float O[8][4] = {};
    float lacc[2] = {0.f, 0.f};      // partial l for row-halves (ra.., rb..)

    const int NTILE = (T2 + 31) / 32;   // 25
    for (int i = 0; i < NTILE; i++) {
        const int buf = i % 3;
        const int kk0 = i * 32;
        asm volatile("cp.async.wait_group 1;");
        __syncthreads();

        // ---- S = Q @ K'^T (exp2 domain; scale folded into kp) ----
        float S[4][4] = {};
        const float* Kc = Ks[buf];
        #pragma unroll
        for (int kb = 0; kb < 8; kb++) {
            #pragma unroll
            for (int nt = 0; nt < 4; nt++) {
                int n = nt*8 + g;
                uint32_t b0 = __float_as_uint(Kc[n*64 + (((kb*2    ) ^ (n & 7)) << 2) + t]);
                uint32_t b1 = __float_as_uint(Kc[n*64 + (((kb*2 + 1) ^ (n & 7)) << 2) + t]);
                mma8(S[nt], qa[kb], b0, b1);
            }
        }

        // ---- mask padded keys (last tile only) ----
        if (kk0 + 32 > T2) {
            #pragma unroll
            for (int nt = 0; nt < 4; nt++) {
                int c0 = kk0 + nt*8 + 2*t;
                if (c0 >= T2)     { S[nt][0] = -1e30f; S[nt][2] = -1e30f; }
                if (c0 + 1 >= T2) { S[nt][1] = -1e30f; S[nt][3] = -1e30f; }
            }
        }

        // ---- P = exp2(S); accumulate partial l (no max, no rescale) ----
        #pragma unroll
        for (int nt = 0; nt < 4; nt++) {
            float e0 = exp2f(S[nt][0]);
            float e1 = exp2f(S[nt][1]);
            float e2 = exp2f(S[nt][2]);
            float e3 = exp2f(S[nt][3]);
            S[nt][0] = e0; S[nt][1] = e1;
            S[nt][2] = e2; S[nt][3] = e3;
            lacc[0] += e0 + e1;
            lacc[1] += e2 + e3;
        }

        // ---- O += P @ V (P A-frags from S via verified lane permutation) ----
        const int L0 = (lane & 28) | (t >> 1);
        const int L2 = L0 + 2;
        const bool odd = (t & 1);
        const float* Vc = Vs[buf];
        #pragma unroll
        for (int kb = 0; kb < 4; kb++) {
            float e0 = __shfl_sync(0xffffffffu, S[kb][0], L0);
            float e1 = __shfl_sync(0xffffffffu, S[kb][1], L0);
            float f0 = __shfl_sync(0xffffffffu, S[kb][2], L0);
            float f1 = __shfl_sync(0xffffffffu, S[kb][3], L0);
            float h0 = __shfl_sync(0xffffffffu, S[kb][0], L2);
            float h1 = __shfl_sync(0xffffffffu, S[kb][1], L2);
            float i0 = __shfl_sync(0xffffffffu, S[kb][2], L2);
            float i1 = __shfl_sync(0xffffffffu, S[kb][3], L2);
            uint32_t pa[4];
            pa[0] = __float_as_uint(odd ? e1 : e0);
            pa[1] = __float_as_uint(odd ? f1 : f0);
            pa[2] = __float_as_uint(odd ? h1 : h0);
            pa[3] = __float_as_uint(odd ? i1 : i0);
            const int vr0 = kb*8 + t;
            const int vr1 = kb*8 + t + 4;
            #pragma unroll
            for (int nt = 0; nt < 8; nt++) {
                int ch0 = nt*2 + (g >> 2);
                int cl  = g & 3;
                uint32_t b0 = __float_as_uint(Vc[vr0*64 + ((ch0 ^ (2*t)) << 2) + cl]);
                uint32_t b1 = __float_as_uint(Vc[vr1*64 + ((ch0 ^ (2*t)) << 2) + cl]);
                mma8(O[nt], pa, b0, b1);
            }
        }

        if (i + 2 < NTILE) load_kv((i + 2) % 3, (i + 2) * 32);
        else cpa_commit();
    }

    // ---- single deferred l reduction (4 lanes sharing a row) ----
    lacc[0] += __shfl_xor_sync(0xffffffffu, lacc[0], 1);
    lacc[0] += __shfl_xor_sync(0xffffffffu, lacc[0], 2);
    lacc[1] += __shfl_xor_sync(0xffffffffu, lacc[1], 1);
    lacc[1] += __shfl_xor_sync(0xffffffffu, lacc[1], 2);

    // ---- finalize: O / l, tf32-round (feeds final GEMM) ----
    {
        float inv0 = 1.f / lacc[0];
        float inv1 = 1.f / lacc[1];
        float* o0 = ob_ + ((size_t)b * T1 + ra) * DIMC + h * HD;
        float* o1 = ob_ + ((size_t)b * T1 + rb) * DIMC + h * HD;
        #pragma unroll
        for (int nt = 0; nt < 8; nt++) {
            *(float2*)&o0[nt*8 + 2*t] =
                make_float2(tf32r(O[nt][0] * inv0), tf32r(O[nt][1] * inv0));
            *(float2*)&o1[nt*8 + 2*t] =
                make_float2(tf32r(O[nt][2] * inv1), tf32r(O[nt][3] * inv1));
        }
    }
}

// ---------------- launch -----------------------------------------------------
extern "C" void kernel_launch(void* const* d_in, const int* in_sizes, int n_in,
                              void* d_out, int out_size)
{
    (void)in_sizes; (void)n_in; (void)out_size;
    const float* x      = (const float*)d_in[0];
    const float* conv_q = (const float*)d_in[3];
    const float* bnq_s  = (const float*)d_in[4];
    const float* bnq_b  = (const float*)d_in[5];
    const float* bnq_m  = (const float*)d_in[6];
    const float* bnq_v  = (const float*)d_in[7];
    const float* conv_k = (const float*)d_in[8];
    const float* bnk_s  = (const float*)d_in[9];
    const float* bnk_b  = (const float*)d_in[10];
    const float* bnk_m  = (const float*)d_in[11];
    const float* bnk_v  = (const float*)d_in[12];
    const float* conv_v = (const float*)d_in[13];
    const float* bnv_s  = (const float*)d_in[14];
    const float* bnv_b  = (const float*)d_in[15];
    const float* bnv_m  = (const float*)d_in[16];
    const float* bnv_v  = (const float*)d_in[17];
    const float* wq     = (const float*)d_in[18];
    const float* wk     = (const float*)d_in[19];
    const float* wv     = (const float*)d_in[20];
    const float* w_last = (const float*)d_in[21];
    const float* b_last = (const float*)d_in[22];
    float* out = (float*)d_out;

    float *qf, *kf, *vf, *qp, *kp, *vp, *ob;
    cudaGetSymbolAddress((void**)&qf, g_qf);
    cudaGetSymbolAddress((void**)&kf, g_kf);
    cudaGetSymbolAddress((void**)&vf, g_vf);
    cudaGetSymbolAddress((void**)&qp, g_qp);
    cudaGetSymbolAddress((void**)&kp, g_kp);
    cudaGetSymbolAddress((void**)&vp, g_vp);
    cudaGetSymbolAddress((void**)&ob, g_ob);

    // 1. weight prep
    round_w_k<<<(4 * WN + 255) / 256, 256>>>(wq, wk, wv, w_last);

    // 2. fused convs
    conv_fused<<<B_ * HH + B_ * H2, DIMC>>>(
        x,
        conv_q, bnq_s, bnq_b, bnq_m, bnq_v,
        conv_k, bnk_s, bnk_b, bnk_m, bnk_v,
        conv_v, bnv_s, bnv_b, bnv_m, bnv_v,
        qf, kf, vf);

    // 3. fused q/k/v projections
    dim3 gproj(DIMC / 64, (B_ * T1) / 128, 3);   // (6, 196, 3)
    proj_fused<<<gproj, 128>>>(qf, kf, vf, qp, kp, vp);

    // 4. attention (64-query tiles, 4 blocks/SM)
    dim3 gattn(T1 / 64, NHEADS, B_);             // (49, 6, 8)
    attn_cp<<<gattn, 128>>>(qp, kp, vp, ob);

    // 5. final projection
    dim3 gbig(DIMC / 64, (B_ * T1) / 128);       // (6, 196)
    proj_last<<<gbig, 128>>>(ob, b_last, out);
}

// round 15
// speedup vs baseline: 1.1365x; 1.1365x over previous
#include <cuda_runtime.h>
#include <math.h>
#include <stdint.h>

#define DIMC 384
#define B_   8
#define HH   56
#define WW   56
#define T1   3136
#define H2   28
#define W2   28
#define T2   784
#define NHEADS 6
#define HD   64
#define EPSBN 1e-5f
#define ATT_SCALE 0.05103103630798288f   /* 384^-0.5 (full dim, per reference) */
#define LOG2E 1.4426950408889634f
#define WN (DIMC * DIMC)

// ---------------- scratch ---------------------------------------------------
__device__ float g_qf[B_ * T1 * DIMC];
__device__ float g_kf[B_ * T2 * DIMC];
__device__ float g_vf[B_ * T2 * DIMC];
__device__ float g_qp[B_ * T1 * DIMC];
__device__ float g_kp[B_ * T2 * DIMC];
__device__ float g_vp[B_ * T2 * DIMC];
__device__ float g_ob[B_ * T1 * DIMC];
__device__ float g_wr[4 * WN];          // tf32-rounded wq, wk, wv, w_last

// ---------------- helpers ---------------------------------------------------
__device__ __forceinline__ float tf32r(float x) {
    uint32_t u;
    asm("cvt.rna.tf32.f32 %0, %1;" : "=r"(u) : "f"(x));
    return __uint_as_float(u);
}

__device__ __forceinline__ void mma8(float* d, const uint32_t* a, uint32_t b0, uint32_t b1) {
    asm volatile(
        "mma.sync.aligned.m16n8k8.row.col.f32.tf32.tf32.f32 "
        "{%0,%1,%2,%3}, {%4,%5,%6,%7}, {%8,%9}, {%0,%1,%2,%3};\n"
        : "+f"(d[0]), "+f"(d[1]), "+f"(d[2]), "+f"(d[3])
        : "r"(a[0]), "r"(a[1]), "r"(a[2]), "r"(a[3]), "r"(b0), "r"(b1));
}

__device__ __forceinline__ void cpa16(uint32_t dst, const void* src) {
    asm volatile("cp.async.cg.shared.global [%0], [%1], 16;" :: "r"(dst), "l"(src));
}
__device__ __forceinline__ void cpa16z(uint32_t dst, const void* src, int sz) {
    asm volatile("cp.async.cg.shared.global [%0], [%1], 16, %2;" :: "r"(dst), "l"(src), "r"(sz));
}
__device__ __forceinline__ void cpa_commit() {
    asm volatile("cp.async.commit_group;");
}
__device__ __forceinline__ uint32_t smem_u32(const void* p) {
    return (uint32_t)__cvta_generic_to_shared(p);
}

// ---------------- prep: round weight matrices to tf32 ------------------------
__global__ __launch_bounds__(256) void round_w_k(
    const float* __restrict__ wq, const float* __restrict__ wk,
    const float* __restrict__ wv, const float* __restrict__ wl)
{
    int i = blockIdx.x * 256 + threadIdx.x;
    if (i < 4 * WN) {
        int m = i / WN, j = i - m * WN;
        const float* s = (m == 0) ? wq : (m == 1) ? wk : (m == 2) ? wv : wl;
        g_wr[i] = tf32r(s[j]);
    }
}

// ---------------- conv bodies ------------------------------------------------
__device__ __forceinline__ void dwconv_s1_body(
    int by,
    const float* __restrict__ x, const float* __restrict__ cw,
    const float* __restrict__ gs, const float* __restrict__ gb,
    const float* __restrict__ gm, const float* __restrict__ gv,
    float* __restrict__ out)
{
    const int b  = by / HH, y = by % HH;
    const int c  = threadIdx.x;

    const float w0 = cw[c*9+0], w1 = cw[c*9+1], w2 = cw[c*9+2];
    const float w3 = cw[c*9+3], w4 = cw[c*9+4], w5 = cw[c*9+5];
    const float w6 = cw[c*9+6], w7 = cw[c*9+7], w8 = cw[c*9+8];
    const float inv = rsqrtf(gv[c] + EPSBN);
    const float sc  = gs[c] * inv;
    const float bb  = gb[c] - gm[c] * sc;

    const float* base = x + (size_t)b * T1 * DIMC + c;
    const bool v0 = (y > 0), v2 = (y < HH - 1);
    const float* r0 = base + (size_t)(y - 1) * WW * DIMC;
    const float* r1 = base + (size_t)y * WW * DIMC;
    const float* r2 = base + (size_t)(y + 1) * WW * DIMC;
    float* op = out + ((size_t)b * T1 + (size_t)y * WW) * DIMC + c;

    float a0 = 0.f, a1 = 0.f, a2 = 0.f;
    float b0 = v0 ? r0[0] : 0.f;
    float b1 = r1[0];
    float b2 = v2 ? r2[0] : 0.f;
    float c0 = v0 ? r0[DIMC] : 0.f;
    float c1 = r1[DIMC];
    float c2 = v2 ? r2[DIMC] : 0.f;

    #pragma unroll 4
    for (int xw = 0; xw < WW; xw++) {
        float acc = a0*w0 + b0*w1 + c0*w2
                  + a1*w3 + b1*w4 + c1*w5
                  + a2*w6 + b2*w7 + c2*w8;
        op[(size_t)xw * DIMC] = tf32r(acc * sc + bb);
        a0 = b0; a1 = b1; a2 = b2;
        b0 = c0; b1 = c1; b2 = c2;
        if (xw + 2 < WW) {
            size_t off = (size_t)(xw + 2) * DIMC;
            c0 = v0 ? r0[off] : 0.f;
            c1 = r1[off];
            c2 = v2 ? r2[off] : 0.f;
        } else { c0 = c1 = c2 = 0.f; }
    }
}

__device__ __forceinline__ void dwconv_s2_body(
    int by,
    const float* __restrict__ x,
    const float* __restrict__ cwk, const float* __restrict__ ksc, const float* __restrict__ kbi,
    const float* __restrict__ kmu, const float* __restrict__ kva,
    const float* __restrict__ cwv, const float* __restrict__ vsc, const float* __restrict__ vbi,
    const float* __restrict__ vmu, const float* __restrict__ vva,
    float* __restrict__ outk, float* __restrict__ outv)
{
    const int b  = by / H2, oy = by % H2;
    const int c  = threadIdx.x;
    const int y  = 2 * oy;

    float wk[9], wv[9];
    #pragma unroll
    for (int i = 0; i < 9; i++) { wk[i] = cwk[c*9+i]; wv[i] = cwv[c*9+i]; }
    const float invk = rsqrtf(kva[c] + EPSBN);
    const float sck  = ksc[c] * invk;
    const float bbk  = kbi[c] - kmu[c] * sck;
    const float invv = rsqrtf(vva[c] + EPSBN);
    const float scv  = vsc[c] * invv;
    const float bbv  = vbi[c] - vmu[c] * scv;

    const float* base = x + (size_t)b * T1 * DIMC + c;
    const bool v0 = (y > 0), v2 = (y < HH - 1);
    const float* r0 = base + (size_t)(y - 1) * WW * DIMC;
    const float* r1 = base + (size_t)y * WW * DIMC;
    const float* r2 = base + (size_t)(y + 1) * WW * DIMC;
    float* opk = outk + ((size_t)b * T2 + (size_t)oy * W2) * DIMC + c;
    float* opv = outv + ((size_t)b * T2 + (size_t)oy * W2) * DIMC + c;

    float a0 = 0.f, a1 = 0.f, a2 = 0.f;
    float b0 = v0 ? r0[0] : 0.f, b1 = r1[0], b2 = v2 ? r2[0] : 0.f;
    float c0 = v0 ? r0[DIMC] : 0.f, c1 = r1[DIMC], c2 = v2 ? r2[DIMC] : 0.f;

    #pragma unroll 2
    for (int ox = 0; ox < W2; ox++) {
        float ak = a0*wk[0] + b0*wk[1] + c0*wk[2]
                 + a1*wk[3] + b1*wk[4] + c1*wk[5]
                 + a2*wk[6] + b2*wk[7] + c2*wk[8];
        float av = a0*wv[0] + b0*wv[1] + c0*wv[2]
                 + a1*wv[3] + b1*wv[4] + c1*wv[5]
                 + a2*wv[6] + b2*wv[7] + c2*wv[8];
        opk[(size_t)ox * DIMC] = tf32r(ak * sck + bbk);
        opv[(size_t)ox * DIMC] = tf32r(av * scv + bbv);
        if (ox + 1 < W2) {
            size_t o1 = (size_t)(2*ox + 2) * DIMC;
            size_t o2 = (size_t)(2*ox + 3) * DIMC;
            a0 = c0; a1 = c1; a2 = c2;
            b0 = v0 ? r0[o1] : 0.f; b1 = r1[o1]; b2 = v2 ? r2[o1] : 0.f;
            c0 = v0 ? r0[o2] : 0.f; c1 = r1[o2]; c2 = v2 ? r2[o2] : 0.f;
        }
    }
}

__global__ __launch_bounds__(DIMC) void conv_fused(
    const float* __restrict__ x,
    const float* __restrict__ cq,  const float* __restrict__ qsc, const float* __restrict__ qbi,
    const float* __restrict__ qmu, const float* __restrict__ qva,
    const float* __restrict__ cwk, const float* __restrict__ ksc, const float* __restrict__ kbi,
    const float* __restrict__ kmu, const float* __restrict__ kva,
    const float* __restrict__ cwv, const float* __restrict__ vsc, const float* __restrict__ vbi,
    const float* __restrict__ vmu, const float* __restrict__ vva,
    float* __restrict__ outq, float* __restrict__ outk, float* __restrict__ outv)
{
    const int bx = blockIdx.x;
    if (bx < B_ * HH) {
        dwconv_s1_body(bx, x, cq, qsc, qbi, qmu, qva, outq);
    } else {
        dwconv_s2_body(bx - B_ * HH, x, cwk, ksc, kbi, kmu, kva,
                       cwv, vsc, vbi, vmu, vva, outk, outv);
    }
}

// ---------------- tf32 GEMM: 128x128 block, 64x64 warp tiles -----------------
// 128 threads / 4 warps (2x2), BK=32, 2-stage cp.async, XOR swizzle.
// 128 MMAs per warp per k-step between barriers; MAC/smem-byte = 8.
__device__ __forceinline__ void gemm_body(
    const float* __restrict__ A, const float* __restrict__ W,
    const float* __restrict__ bias, float* __restrict__ C,
    float oscale, int rnd, int row0, int col0)
{
    __shared__ float As[2][128 * 32];
    __shared__ float Ws[2][128 * 32];

    const int tid = threadIdx.x;
    const int w = tid >> 5, lane = tid & 31;
    const int g = lane >> 2, t = lane & 3;
    const int wm = (w & 1) * 64, wn = (w >> 1) * 64;

    float acc[4][8][4] = {};

    auto load_stage = [&](int s, int k0) {
        uint32_t abase = smem_u32(As[s]);
        uint32_t wbase = smem_u32(Ws[s]);
        #pragma unroll
        for (int p = 0; p < 8; p++) {
            int idx = tid + p * 128;
            int r = idx >> 3, j = idx & 7;
            uint32_t off = r * 128 + ((j ^ (r & 7)) << 4);
            cpa16(abase + off, A + (size_t)(row0 + r) * DIMC + k0 + j * 4);
            cpa16(wbase + off, W + (size_t)(col0 + r) * DIMC + k0 + j * 4);
        }
        cpa_commit();
    };

    load_stage(0, 0);
    load_stage(1, 32);

    for (int ks = 0; ks < 12; ks++) {
        const int s = ks & 1;
        asm volatile("cp.async.wait_group 1;");
        __syncthreads();
        const float* Ac = As[s];
        const float* Wc = Ws[s];
        #pragma unroll
        for (int kb = 0; kb < 4; kb++) {
            const int c0i = (((kb*2    ) ^ g) << 2) + t;
            const int c1i = (((kb*2 + 1) ^ g) << 2) + t;
            uint32_t af[4][4];
            #pragma unroll
            for (int mi = 0; mi < 4; mi++) {
                int r0i = wm + mi*16 + g;
                af[mi][0] = __float_as_uint(Ac[ r0i      * 32 + c0i]);
                af[mi][1] = __float_as_uint(Ac[(r0i + 8) * 32 + c0i]);
                af[mi][2] = __float_as_uint(Ac[ r0i      * 32 + c1i]);
                af[mi][3] = __float_as_uint(Ac[(r0i + 8) * 32 + c1i]);
            }
            #pragma unroll
            for (int ni = 0; ni < 8; ni++) {
                int nr = wn + ni*8 + g;
                uint32_t b0 = __float_as_uint(Wc[nr * 32 + c0i]);
                uint32_t b1 = __float_as_uint(Wc[nr * 32 + c1i]);
                #pragma unroll
                for (int mi = 0; mi < 4; mi++) mma8(acc[mi][ni], af[mi], b0, b1);
            }
        }
        __syncthreads();
        if (ks + 2 < 12) load_stage(s, (ks + 2) * 32);
        else cpa_commit();
    }

    #pragma unroll
    for (int mi = 0; mi < 4; mi++) {
        int r0 = row0 + wm + mi*16 + g;
        #pragma unroll
        for (int ni = 0; ni < 8; ni++) {
            int cc = col0 + wn + ni*8 + 2*t;
            float b0f = 0.f, b1f = 0.f;
            if (bias) { b0f = bias[cc]; b1f = bias[cc+1]; }
            float v0 = acc[mi][ni][0] * oscale + b0f;
            float v1 = acc[mi][ni][1] * oscale + b1f;
            float v2 = acc[mi][ni][2] * oscale + b0f;
            float v3 = acc[mi][ni][3] * oscale + b1f;
            if (rnd) { v0 = tf32r(v0); v1 = tf32r(v1); v2 = tf32r(v2); v3 = tf32r(v3); }
            *(float2*)&C[(size_t)r0 * DIMC + cc]       = make_float2(v0, v1);
            *(float2*)&C[(size_t)(r0 + 8) * DIMC + cc] = make_float2(v2, v3);
        }
    }
}

__global__ __launch_bounds__(128) void proj_fused(
    const float* __restrict__ qf, const float* __restrict__ kf,
    const float* __restrict__ vf,
    float* __restrict__ qp, float* __restrict__ kp, float* __restrict__ vp)
{
    const int z  = blockIdx.z;
    const int by = blockIdx.y;
    if (z > 0 && by >= (B_ * T2) / 128) return;

    const float* A = (z == 0) ? qf : (z == 1) ? kf : vf;
    const float* W = g_wr + z * WN;
    float*       C = (z == 0) ? qp : (z == 1) ? kp : vp;
    const float oscale = (z == 1) ? (ATT_SCALE * LOG2E) : 1.0f;

    gemm_body(A, W, nullptr, C, oscale, 1, by * 128, blockIdx.x * 128);
}

__global__ __launch_bounds__(128) void proj_last(
    const float* __restrict__ ob, const float* __restrict__ bias,
    float* __restrict__ out)
{
    gemm_body(ob, g_wr + 3 * WN, bias, out, 1.0f, 0,
              blockIdx.y * 128, blockIdx.x * 128);
}

// ---------------- tf32 flash attention (round-12 verified, 174.8us) ----------
// m=32/warp, 128-query blocks, no-max streaming softmax, 3 KV buffers,
// 1 barrier per tile.
__global__ __launch_bounds__(128, 2) void attn_cp(
    const float* __restrict__ qp_, const float* __restrict__ kp_,
    const float* __restrict__ vp_, float* __restrict__ ob_)
{
    __shared__ float Ks[3][32 * 64];
    __shared__ float Vs[3][32 * 64];

    const int tid = threadIdx.x;
    const int w = tid >> 5, lane = tid & 31;
    const int g = lane >> 2, t = lane & 3;
    const int q0 = blockIdx.x * 128;
    const int h  = blockIdx.y;
    const int b  = blockIdx.z;

    const float* qp = qp_ + (size_t)b * T1 * DIMC + h * HD;
    const float* kp = kp_ + (size_t)b * T2 * DIMC + h * HD;
    const float* vp = vp_ + (size_t)b * T2 * DIMC + h * HD;

    const int kr = tid >> 4;
    const int kj = tid & 15;

    auto load_kv = [&](int buf, int kk0) {
        uint32_t kbase = smem_u32(Ks[buf]);
        uint32_t vbase = smem_u32(Vs[buf]);
        #pragma unroll
        for (int p = 0; p < 4; p++) {
            int r = kr + 8 * p;
            int key = kk0 + r;
            int ok  = (key < T2) ? 16 : 0;
            int kcl = (key < T2) ? key : (T2 - 1);
            cpa16z(kbase + r * 256 + ((kj ^ (r & 7)) << 4),
                   kp + (size_t)kcl * DIMC + kj * 4, ok);
            cpa16z(vbase + r * 256 + ((kj ^ (2 * (r & 3))) << 4),
                   vp + (size_t)kcl * DIMC + kj * 4, ok);
        }
        cpa_commit();
    };

    load_kv(0, 0);
    load_kv(1, 32);

    const int rbase = q0 + w * 32;
    uint32_t qa[2][8][4];
    #pragma unroll
    for (int s = 0; s < 2; s++) {
        int ra = rbase + s*16 + g;
        int rb = ra + 8;
        const float* pa = qp + (size_t)(ra < T1 ? ra : T1-1) * DIMC;
        const float* pb = qp + (size_t)(rb < T1 ? rb : T1-1) * DIMC;
        #pragma unroll
        for (int kb = 0; kb < 8; kb++) {
            qa[s][kb][0] = __float_as_uint(pa[kb*8 + t]);
            qa[s][kb][1] = __float_as_uint(pb[kb*8 + t]);
            qa[s][kb][2] = __float_as_uint(pa[kb*8 + t + 4]);
            qa[s][kb][3] = __float_as_uint(pb[kb*8 + t + 4]);
        }
    }

    float O[2][8][4] = {};
    float lacc[4] = {0.f, 0.f, 0.f, 0.f};

    const int NTILE = (T2 + 31) / 32;
    for (int i = 0; i < NTILE; i++) {
        const int buf = i % 3;
        const int kk0 = i * 32;
        asm volatile("cp.async.wait_group 1;");
        __syncthreads();

        float S[2][4][4] = {};
        const float* Kc = Ks[buf];
        #pragma unroll
        for (int kb = 0; kb < 8; kb++) {
            #pragma unroll
            for (int nt = 0; nt < 4; nt++) {
                int n = nt*8 + g;
                uint32_t b0 = __float_as_uint(Kc[n*64 + (((kb*2    ) ^ (n & 7)) << 2) + t]);
                uint32_t b1 = __float_as_uint(Kc[n*64 + (((kb*2 + 1) ^ (n & 7)) << 2) + t]);
                mma8(S[0][nt], qa[0][kb], b0, b1);
                mma8(S[1][nt], qa[1][kb], b0, b1);
            }
        }

        if (kk0 + 32 > T2) {
            #pragma unroll
            for (int nt = 0; nt < 4; nt++) {
                int c0 = kk0 + nt*8 + 2*t;
                if (c0 >= T2)     { S[0][nt][0] = -1e30f; S[0][nt][2] = -1e30f;
                                    S[1][nt][0] = -1e30f; S[1][nt][2] = -1e30f; }
                if (c0 + 1 >= T2) { S[0][nt][1] = -1e30f; S[0][nt][3] = -1e30f;
                                    S[1][nt][1] = -1e30f; S[1][nt][3] = -1e30f; }
            }
        }

        #pragma unroll
        for (int s = 0; s < 2; s++) {
            #pragma unroll
            for (int nt = 0; nt < 4; nt++) {
                float e0 = exp2f(S[s][nt][0]);
                float e1 = exp2f(S[s][nt][1]);
                float e2 = exp2f(S[s][nt][2]);
                float e3 = exp2f(S[s][nt][3]);
                S[s][nt][0] = e0; S[s][nt][1] = e1;
                S[s][nt][2] = e2; S[s][nt][3] = e3;
                lacc[s*2 + 0] += e0 + e1;
                lacc[s*2 + 1] += e2 + e3;
            }
        }

        const int L0 = (lane & 28) | (t >> 1);
        const int L2 = L0 + 2;
        const bool odd = (t & 1);
        const float* Vc = Vs[buf];
        #pragma unroll
        for (int kb = 0; kb < 4; kb++) {
            uint32_t pa[2][4];
            #pragma unroll
            for (int s = 0; s < 2; s++) {
                float e0 = __shfl_sync(0xffffffffu, S[s][kb][0], L0);
                float e1 = __shfl_sync(0xffffffffu, S[s][kb][1], L0);
                float f0 = __shfl_sync(0xffffffffu, S[s][kb][2], L0);
                float f1 = __shfl_sync(0xffffffffu, S[s][kb][3], L0);
                float h0 = __shfl_sync(0xffffffffu, S[s][kb][0], L2);
                float h1 = __shfl_sync(0xffffffffu, S[s][kb][1], L2);
                float i0 = __shfl_sync(0xffffffffu, S[s][kb][2], L2);
                float i1 = __shfl_sync(0xffffffffu, S[s][kb][3], L2);
                pa[s][0] = __float_as_uint(odd ? e1 : e0);
                pa[s][1] = __float_as_uint(odd ? f1 : f0);
                pa[s][2] = __float_as_uint(odd ? h1 : h0);
                pa[s][3] = __float_as_uint(odd ? i1 : i0);
            }
            const int vr0 = kb*8 + t;
            const int vr1 = kb*8 + t + 4;
            #pragma unroll
            for (int nt = 0; nt < 8; nt++) {
                int ch0 = nt*2 + (g >> 2);
                int cl  = g & 3;
                uint32_t b0 = __float_as_uint(Vc[vr0*64 + ((ch0 ^ (2*t)) << 2) + cl]);
                uint32_t b1 = __float_as_uint(Vc[vr1*64 + ((ch0 ^ (2*t)) << 2) + cl]);
                mma8(O[0][nt], pa[0], b0, b1);
                mma8(O[1][nt], pa[1], b0, b1);
            }
        }

        if (i + 2 < NTILE) load_kv((i + 2) % 3, (i + 2) * 32);
        else cpa_commit();
    }

    #pragma unroll
    for (int rc = 0; rc < 4; rc++) {
        lacc[rc] += __shfl_xor_sync(0xffffffffu, lacc[rc], 1);
        lacc[rc] += __shfl_xor_sync(0xffffffffu, lacc[rc], 2);
    }

    #pragma unroll
    for (int s = 0; s < 2; s++) {
        float inv0 = 1.f / lacc[s*2 + 0];
        float inv1 = 1.f / lacc[s*2 + 1];
        int r0 = rbase + s*16 + g;
        int r1 = r0 + 8;
        if (r0 < T1) {
            float* o0 = ob_ + ((size_t)b * T1 + r0) * DIMC + h * HD;
            #pragma unroll
            for (int nt = 0; nt < 8; nt++)
                *(float2*)&o0[nt*8 + 2*t] =
                    make_float2(tf32r(O[s][nt][0] * inv0), tf32r(O[s][nt][1] * inv0));
        }
        if (r1 < T1) {
            float* o1 = ob_ + ((size_t)b * T1 + r1) * DIMC + h * HD;
            #pragma unroll
            for (int nt = 0; nt < 8; nt++)
                *(float2*)&o1[nt*8 + 2*t] =
                    make_float2(tf32r(O[s][nt][2] * inv1), tf32r(O[s][nt][3] * inv1));
        }
    }
}

// ---------------- launch -----------------------------------------------------
extern "C" void kernel_launch(void* const* d_in, const int* in_sizes, int n_in,
                              void* d_out, int out_size)
{
    (void)in_sizes; (void)n_in; (void)out_size;
    const float* x      = (const float*)d_in[0];
    const float* conv_q = (const float*)d_in[3];
    const float* bnq_s  = (const float*)d_in[4];
    const float* bnq_b  = (const float*)d_in[5];
    const float* bnq_m  = (const float*)d_in[6];
    const float* bnq_v  = (const float*)d_in[7];
    const float* conv_k = (const float*)d_in[8];
    const float* bnk_s  = (const float*)d_in[9];
    const float* bnk_b  = (const float*)d_in[10];
    const float* bnk_m  = (const float*)d_in[11];
    const float* bnk_v  = (const float*)d_in[12];
    const float* conv_v = (const float*)d_in[13];
    const float* bnv_s  = (const float*)d_in[14];
    const float* bnv_b  = (const float*)d_in[15];
    const float* bnv_m  = (const float*)d_in[16];
    const float* bnv_v  = (const float*)d_in[17];
    const float* wq     = (const float*)d_in[18];
    const float* wk     = (const float*)d_in[19];
    const float* wv     = (const float*)d_in[20];
    const float* w_last = (const float*)d_in[21];
    const float* b_last = (const float*)d_in[22];
    float* out = (float*)d_out;

    float *qf, *kf, *vf, *qp, *kp, *vp, *ob;
    cudaGetSymbolAddress((void**)&qf, g_qf);
    cudaGetSymbolAddress((void**)&kf, g_kf);
    cudaGetSymbolAddress((void**)&vf, g_vf);
    cudaGetSymbolAddress((void**)&qp, g_qp);
    cudaGetSymbolAddress((void**)&kp, g_kp);
    cudaGetSymbolAddress((void**)&vp, g_vp);
    cudaGetSymbolAddress((void**)&ob, g_ob);

    // 1. weight prep
    round_w_k<<<(4 * WN + 255) / 256, 256>>>(wq, wk, wv, w_last);

    // 2. fused convs
    conv_fused<<<B_ * HH + B_ * H2, DIMC>>>(
        x,
        conv_q, bnq_s, bnq_b, bnq_m, bnq_v,
        conv_k, bnk_s, bnk_b, bnk_m, bnk_v,
        conv_v, bnv_s, bnv_b, bnv_m, bnv_v,
        qf, kf, vf);

    // 3. fused q/k/v projections (128x128 tiles)
    dim3 gproj(DIMC / 128, (B_ * T1) / 128, 3);   // (3, 196, 3)
    proj_fused<<<gproj, 128>>>(qf, kf, vf, qp, kp, vp);

    // 4. attention (round-12 config)
    dim3 gattn((T1 + 127) / 128, NHEADS, B_);     // (25, 6, 8)
    attn_cp<<<gattn, 128>>>(qp, kp, vp, ob);

    // 5. final projection (128x128 tiles)
    dim3 gbig(DIMC / 128, (B_ * T1) / 128);       // (3, 196)
    proj_last<<<gbig, 128>>>(ob, b_last, out);
}